// round 1
// baseline (speedup 1.0000x reference)
#include <cuda_runtime.h>
#include <cuda_bf16.h>

// Problem constants (fixed by the dataset)
#define N_OUT_MAX 400000
#define COUT 64
#define KK 108            // 27 neighbors * 4 input channels
#define TILE_N 64
#define CONV_THREADS 256
#define CONV_SMEM (KK*COUT*4*2 + TILE_N*27*4)   // Wsm + Gsm + Ism = 62208 B

// Scratch: y [N_out, 64] plus BN statistics / affine params.
__device__ float g_y[N_OUT_MAX * COUT];
__device__ float g_sum[COUT];
__device__ float g_sumsq[COUT];
__device__ float g_scale[COUT];
__device__ float g_shift[COUT];

__global__ void zero_stats_kernel() {
    int t = threadIdx.x;
    if (t < COUT) { g_sum[t] = 0.0f; g_sumsq[t] = 0.0f; }
}

// Conv (implicit GEMM) + per-channel sum / sumsq accumulation.
// Tile: 64 nodes x 64 channels per block; thread = 4 nodes x 4 channels.
extern "C" __global__ void __launch_bounds__(CONV_THREADS)
conv_kernel(const float4* __restrict__ x,      // [N_in, 4] as float4 rows
            const float*  __restrict__ w,      // [27, 4, 64] row-major = [108, 64]
            const int*    __restrict__ nidx,   // [N_out, 27]
            int n_out)
{
    extern __shared__ float sm[];
    float* Wsm = sm;                 // [108][64]
    float* Gsm = sm + KK * COUT;     // [108][64]  (k-major gathered tile)
    int*   Ism = (int*)(sm + 2 * KK * COUT);  // [64*27]

    const int tid = threadIdx.x;
    const int nbase = blockIdx.x * TILE_N;

    // Load weights (coalesced, 27 floats/thread)
    #pragma unroll
    for (int i = tid; i < KK * COUT; i += CONV_THREADS)
        Wsm[i] = w[i];

    // Load the neighbor-index tile (coalesced)
    for (int i = tid; i < TILE_N * 27; i += CONV_THREADS) {
        int gi = nbase * 27 + i;
        Ism[i] = (gi < n_out * 27) ? nidx[gi] : 0;
    }
    __syncthreads();

    // Gather x rows into Gsm[k*4+c][n]
    for (int i = tid; i < TILE_N * 27; i += CONV_THREADS) {
        int n = i & (TILE_N - 1);
        int k = i >> 6;
        float4 v = __ldg(&x[Ism[n * 27 + k]]);
        int b = (k << 2) * COUT + n;
        Gsm[b]            = v.x;
        Gsm[b + COUT]     = v.y;
        Gsm[b + 2 * COUT] = v.z;
        Gsm[b + 3 * COUT] = v.w;
    }
    __syncthreads();

    const int tn = tid & 15;   // node group (4 nodes)
    const int to = tid >> 4;   // channel group (4 channels)

    float acc[4][4];
    #pragma unroll
    for (int i = 0; i < 4; i++)
        #pragma unroll
        for (int j = 0; j < 4; j++) acc[i][j] = 0.0f;

    const float4* Gp = ((const float4*)Gsm) + tn;   // stride 16 float4 per kk
    const float4* Wp = ((const float4*)Wsm) + to;

    #pragma unroll 4
    for (int kk = 0; kk < KK; kk++) {
        float4 g = Gp[kk * (COUT / 4)];
        float4 wv = Wp[kk * (COUT / 4)];
        float gv[4] = {g.x, g.y, g.z, g.w};
        float wr[4] = {wv.x, wv.y, wv.z, wv.w};
        #pragma unroll
        for (int i = 0; i < 4; i++)
            #pragma unroll
            for (int j = 0; j < 4; j++)
                acc[i][j] = fmaf(gv[i], wr[j], acc[i][j]);
    }

    // Store y, accumulate per-channel partial sums
    float s[4] = {0, 0, 0, 0}, q[4] = {0, 0, 0, 0};
    #pragma unroll
    for (int i = 0; i < 4; i++) {
        int gn = nbase + tn * 4 + i;
        if (gn < n_out) {
            float4 o4 = make_float4(acc[i][0], acc[i][1], acc[i][2], acc[i][3]);
            *(float4*)&g_y[(size_t)gn * COUT + to * 4] = o4;
            #pragma unroll
            for (int c = 0; c < 4; c++) {
                s[c] += acc[i][c];
                q[c] += acc[i][c] * acc[i][c];
            }
        }
    }
    // Reduce over the 16 lanes that share `to` (offsets < 16 stay in-group)
    #pragma unroll
    for (int off = 8; off >= 1; off >>= 1) {
        #pragma unroll
        for (int c = 0; c < 4; c++) {
            s[c] += __shfl_xor_sync(0xFFFFFFFFu, s[c], off);
            q[c] += __shfl_xor_sync(0xFFFFFFFFu, q[c], off);
        }
    }
    if (tn == 0) {
        #pragma unroll
        for (int c = 0; c < 4; c++) {
            atomicAdd(&g_sum[to * 4 + c], s[c]);
            atomicAdd(&g_sumsq[to * 4 + c], q[c]);
        }
    }
}

__global__ void finalize_kernel(const float* __restrict__ gamma,
                                const float* __restrict__ beta,
                                float inv_n)
{
    int o = threadIdx.x;
    if (o < COUT) {
        float mean = g_sum[o] * inv_n;
        float var = g_sumsq[o] * inv_n - mean * mean;
        float sc = gamma[o] * rsqrtf(var + 1e-5f);
        g_scale[o] = sc;
        g_shift[o] = beta[o] - mean * sc;
    }
}

// Fused BN-affine + ReLU + max over 8 children. Thread = (pool node, 4 channels).
__global__ void __launch_bounds__(256)
pool_kernel(const int* __restrict__ pidx, float* __restrict__ out, int n_pool)
{
    int gid = blockIdx.x * blockDim.x + threadIdx.x;
    int p = gid >> 4;
    int cg = gid & 15;
    if (p >= n_pool) return;

    float4 sc = *(const float4*)&g_scale[cg * 4];
    float4 sh = *(const float4*)&g_shift[cg * 4];
    float4 m = make_float4(0.0f, 0.0f, 0.0f, 0.0f);  // relu >= 0, so 0 is a safe identity

    #pragma unroll
    for (int j = 0; j < 8; j++) {
        int ci = __ldg(&pidx[p * 8 + j]);
        float4 v = *(const float4*)&g_y[(size_t)ci * COUT + cg * 4];
        m.x = fmaxf(m.x, fmaf(v.x, sc.x, sh.x));
        m.y = fmaxf(m.y, fmaf(v.y, sc.y, sh.y));
        m.z = fmaxf(m.z, fmaf(v.z, sc.z, sh.z));
        m.w = fmaxf(m.w, fmaf(v.w, sc.w, sh.w));
    }
    *(float4*)&out[(size_t)p * COUT + cg * 4] = m;
}

// Fill any trailing output slots with (float)(depth - 2).
__global__ void depth_kernel(float* __restrict__ dst, const int* __restrict__ depth, int n) {
    int i = blockIdx.x * blockDim.x + threadIdx.x;
    if (i < n) dst[i] = (float)(depth[0] - 2);
}

extern "C" void kernel_launch(void* const* d_in, const int* in_sizes, int n_in,
                              void* d_out, int out_size)
{
    const float4* x     = (const float4*)d_in[0];
    const float*  w     = (const float*)d_in[1];
    const float*  gamma = (const float*)d_in[2];
    const float*  beta  = (const float*)d_in[3];
    const int*    nidx  = (const int*)d_in[4];
    const int*    pidx  = (const int*)d_in[5];
    const int*    depth = (n_in > 6) ? (const int*)d_in[6] : nullptr;

    int n_out  = in_sizes[4] / 27;
    int n_pool = in_sizes[5] / 8;
    float* out = (float*)d_out;

    cudaFuncSetAttribute(conv_kernel, cudaFuncAttributeMaxDynamicSharedMemorySize, CONV_SMEM);

    zero_stats_kernel<<<1, 64>>>();
    conv_kernel<<<(n_out + TILE_N - 1) / TILE_N, CONV_THREADS, CONV_SMEM>>>(x, w, nidx, n_out);
    finalize_kernel<<<1, 64>>>(gamma, beta, 1.0f / (float)n_out);
    pool_kernel<<<(n_pool * 16 + 255) / 256, 256>>>(pidx, out, n_pool);

    int extra = out_size - n_pool * COUT;
    if (extra > 0 && depth) {
        depth_kernel<<<(extra + 255) / 256, 256>>>(out + (size_t)n_pool * COUT, depth, extra);
    }
}

// round 3
// speedup vs baseline: 1.5873x; 1.5873x over previous
#include <cuda_runtime.h>
#include <cuda_bf16.h>
#include <cstdint>

// ─── problem constants ───────────────────────────────────────────────────
#define COUT        64
#define N_OUT_MAX   400000
#define TILE_M      128
#define KVALID      108              // 27 neighbors * 4 cin
#define KPAD        112              // 14 * 8
#define KSTEPS      14
#define A_STRIDE    116              // floats; bank-conflict-free fragment loads
#define B_STRIDE    72               // floats; bank-conflict-free fragment loads
#define CONV_THREADS 256
#define A_ELEMS     (TILE_M * A_STRIDE)      // 14848
#define B_ELEMS     (KPAD * B_STRIDE)        // 8064
#define CONV_SMEM   ((A_ELEMS + B_ELEMS) * 4)  // 91648 B

// ─── device scratch (no allocs allowed) ──────────────────────────────────
__device__ float g_y[N_OUT_MAX * COUT];
__device__ float g_sum[COUT];
__device__ float g_sumsq[COUT];
__device__ float g_scale[COUT];
__device__ float g_shift[COUT];

__device__ __forceinline__ uint32_t f2tf32(float f) {
    uint32_t r;
    asm("cvt.rna.tf32.f32 %0, %1;" : "=r"(r) : "f"(f));
    return r;
}

__device__ __forceinline__ void mma_tf32(float& c0, float& c1, float& c2, float& c3,
                                         uint32_t a0, uint32_t a1, uint32_t a2, uint32_t a3,
                                         uint32_t b0, uint32_t b1) {
    asm volatile(
        "mma.sync.aligned.m16n8k8.row.col.f32.tf32.tf32.f32 "
        "{%0,%1,%2,%3}, {%4,%5,%6,%7}, {%8,%9}, {%0,%1,%2,%3};"
        : "+f"(c0), "+f"(c1), "+f"(c2), "+f"(c3)
        : "r"(a0), "r"(a1), "r"(a2), "r"(a3), "r"(b0), "r"(b1));
}

__global__ void zero_stats_kernel() {
    int t = threadIdx.x;
    if (t < COUT) { g_sum[t] = 0.0f; g_sumsq[t] = 0.0f; }
}

// ─── tf32 mma.sync implicit-GEMM conv + fused BN statistics ──────────────
// Block: 128 nodes × 64 cout. Warp w owns rows [16w, 16w+16). 8 n-tiles of 8.
extern "C" __global__ void __launch_bounds__(CONV_THREADS)
conv_kernel(const float4* __restrict__ x,
            const float*  __restrict__ w,
            const int*    __restrict__ nidx,
            int n_out)
{
    extern __shared__ uint32_t sm[];
    uint32_t* As = sm;             // [128][116] tf32
    uint32_t* Bs = sm + A_ELEMS;   // [112][72]  tf32 (k-major, B[k][n])

    const int tid = threadIdx.x;
    const int wid = tid >> 5, lane = tid & 31;
    const int nbase = blockIdx.x * TILE_M;
    const int limit = n_out - nbase;             // rows valid in this block

    // Zero A pad columns 108..115 (two float4 per row)
    {
        int r = tid >> 1, half = tid & 1;
        uint4 z = make_uint4(0, 0, 0, 0);
        *reinterpret_cast<uint4*>(&As[r * A_STRIDE + 108 + half * 4]) = z;
    }

    // Fill B: W^T padded — Bs[k][n] = tf32(w[k*64+n]), zeros for k>=108
    #pragma unroll
    for (int j = 0; j < 28; j++) {
        int i = tid + j * CONV_THREADS;           // i in [0, 7168)
        int k = i >> 6, n = i & 63;
        float v = (k < KVALID) ? __ldg(&w[i]) : 0.0f;
        Bs[k * B_STRIDE + n] = f2tf32(v);
    }

    // Gather A: 128 nodes × 27 neighbor float4 rows
    {
        int idxs[14];
        #pragma unroll
        for (int j = 0; j < 14; j++) {
            int i = tid + j * CONV_THREADS;       // i in [0, 3584); valid < 3456
            bool ok = (i < TILE_M * 27) && (i < limit * 27);
            idxs[j] = ok ? __ldg(&nidx[(size_t)nbase * 27 + i]) : -1;
        }
        #pragma unroll
        for (int j = 0; j < 14; j++) {
            int i = tid + j * CONV_THREADS;
            if (idxs[j] >= 0) {
                int n = i / 27, k = i - n * 27;
                float4 v = __ldg(&x[idxs[j]]);
                uint4 t4;
                t4.x = f2tf32(v.x); t4.y = f2tf32(v.y);
                t4.z = f2tf32(v.z); t4.w = f2tf32(v.w);
                *reinterpret_cast<uint4*>(&As[n * A_STRIDE + k * 4]) = t4;
            } else if (i < TILE_M * 27) {
                int n = i / 27, k = i - n * 27;
                *reinterpret_cast<uint4*>(&As[n * A_STRIDE + k * 4]) = make_uint4(0, 0, 0, 0);
            }
        }
    }
    __syncthreads();

    // Mainloop
    const int rA0 = (wid * 16 + (lane >> 2)) * A_STRIDE;
    const int rA1 = rA0 + 8 * A_STRIDE;
    const int cA  = lane & 3;
    const int nB  = lane >> 2;

    float acc[8][4];
    #pragma unroll
    for (int t = 0; t < 8; t++)
        #pragma unroll
        for (int c = 0; c < 4; c++) acc[t][c] = 0.0f;

    #pragma unroll
    for (int ks = 0; ks < KSTEPS; ks++) {
        const int kb = ks * 8;
        uint32_t a0 = As[rA0 + kb + cA];
        uint32_t a1 = As[rA1 + kb + cA];
        uint32_t a2 = As[rA0 + kb + 4 + cA];
        uint32_t a3 = As[rA1 + kb + 4 + cA];
        const uint32_t* Bk0 = &Bs[(kb + cA) * B_STRIDE + nB];
        const uint32_t* Bk1 = &Bs[(kb + 4 + cA) * B_STRIDE + nB];
        #pragma unroll
        for (int t = 0; t < 8; t++) {
            uint32_t b0 = Bk0[t * 8];
            uint32_t b1 = Bk1[t * 8];
            mma_tf32(acc[t][0], acc[t][1], acc[t][2], acc[t][3],
                     a0, a1, a2, a3, b0, b1);
        }
    }

    // Epilogue: store y + warp-reduce per-channel sums
    const int row0 = wid * 16 + (lane >> 2);
    const int row1 = row0 + 8;
    const bool v0 = row0 < limit;
    const bool v1 = row1 < limit;
    const int colb = (lane & 3) * 2;

    float2* yr0 = reinterpret_cast<float2*>(&g_y[((size_t)nbase + row0) * COUT + colb]);
    float2* yr1 = reinterpret_cast<float2*>(&g_y[((size_t)nbase + row1) * COUT + colb]);
    #pragma unroll
    for (int t = 0; t < 8; t++) {
        if (v0) yr0[t * 4] = make_float2(acc[t][0], acc[t][1]);
        if (v1) yr1[t * 4] = make_float2(acc[t][2], acc[t][3]);
    }

    // stats: channel(ch0)=colb+8t, ch1=colb+8t+1; rows 0/1 from c0/c2 and c1/c3
    __syncthreads();                 // done with A/B tiles; reuse smem for stats
    float* ss = reinterpret_cast<float*>(sm);        // [64]
    float* sq = reinterpret_cast<float*>(sm) + 64;   // [64]
    if (tid < 128) reinterpret_cast<float*>(sm)[tid] = 0.0f;
    __syncthreads();

    #pragma unroll
    for (int t = 0; t < 8; t++) {
        float s0 = (v0 ? acc[t][0] : 0.f) + (v1 ? acc[t][2] : 0.f);
        float s1 = (v0 ? acc[t][1] : 0.f) + (v1 ? acc[t][3] : 0.f);
        float q0 = (v0 ? acc[t][0] * acc[t][0] : 0.f) + (v1 ? acc[t][2] * acc[t][2] : 0.f);
        float q1 = (v0 ? acc[t][1] * acc[t][1] : 0.f) + (v1 ? acc[t][3] * acc[t][3] : 0.f);
        #pragma unroll
        for (int off = 4; off < 32; off <<= 1) {
            s0 += __shfl_xor_sync(0xFFFFFFFFu, s0, off);
            s1 += __shfl_xor_sync(0xFFFFFFFFu, s1, off);
            q0 += __shfl_xor_sync(0xFFFFFFFFu, q0, off);
            q1 += __shfl_xor_sync(0xFFFFFFFFu, q1, off);
        }
        if (lane < 4) {
            int ch = t * 8 + colb;
            atomicAdd(&ss[ch],     s0);
            atomicAdd(&ss[ch + 1], s1);
            atomicAdd(&sq[ch],     q0);
            atomicAdd(&sq[ch + 1], q1);
        }
    }
    __syncthreads();
    if (tid < COUT) {
        atomicAdd(&g_sum[tid],   ss[tid]);
        atomicAdd(&g_sumsq[tid], sq[tid]);
    }
}

__global__ void finalize_kernel(const float* __restrict__ gamma,
                                const float* __restrict__ beta, float inv_n) {
    int o = threadIdx.x;
    if (o < COUT) {
        float mean = g_sum[o] * inv_n;
        float var  = g_sumsq[o] * inv_n - mean * mean;
        float sc   = gamma[o] * rsqrtf(var + 1e-5f);
        g_scale[o] = sc;
        g_shift[o] = beta[o] - mean * sc;
    }
}

// BN-affine + ReLU + max over 8 children, fused
__global__ void __launch_bounds__(256)
pool_kernel(const int* __restrict__ pidx, float* __restrict__ out, int n_pool) {
    int gid = blockIdx.x * blockDim.x + threadIdx.x;
    int p = gid >> 4, cg = gid & 15;
    if (p >= n_pool) return;
    float4 sc = *reinterpret_cast<const float4*>(&g_scale[cg * 4]);
    float4 sh = *reinterpret_cast<const float4*>(&g_shift[cg * 4]);
    float4 m = make_float4(0.f, 0.f, 0.f, 0.f);   // ReLU floor
    #pragma unroll
    for (int j = 0; j < 8; j++) {
        int ci = __ldg(&pidx[p * 8 + j]);
        float4 v = *reinterpret_cast<const float4*>(&g_y[(size_t)ci * COUT + cg * 4]);
        m.x = fmaxf(m.x, fmaf(v.x, sc.x, sh.x));
        m.y = fmaxf(m.y, fmaf(v.y, sc.y, sh.y));
        m.z = fmaxf(m.z, fmaf(v.z, sc.z, sh.z));
        m.w = fmaxf(m.w, fmaf(v.w, sc.w, sh.w));
    }
    *reinterpret_cast<float4*>(&out[(size_t)p * COUT + cg * 4]) = m;
}

__global__ void depth_kernel(float* __restrict__ dst, const int* __restrict__ depth, int n) {
    int i = blockIdx.x * blockDim.x + threadIdx.x;
    if (i < n) dst[i] = (float)(depth[0] - 2);
}

// ─── launch ──────────────────────────────────────────────────────────────
extern "C" void kernel_launch(void* const* d_in, const int* in_sizes, int n_in,
                              void* d_out, int out_size)
{
    const float4* x     = (const float4*)d_in[0];
    const float*  w     = (const float*)d_in[1];
    const float*  gamma = (const float*)d_in[2];
    const float*  beta  = (const float*)d_in[3];
    const int*    nidx  = (const int*)d_in[4];
    const int*    pidx  = (const int*)d_in[5];
    const int*    depth = (n_in > 6) ? (const int*)d_in[6] : nullptr;

    int n_out  = in_sizes[4] / 27;
    int n_pool = in_sizes[5] / 8;
    float* out = (float*)d_out;

    cudaFuncSetAttribute(conv_kernel, cudaFuncAttributeMaxDynamicSharedMemorySize, CONV_SMEM);

    zero_stats_kernel<<<1, 64>>>();
    conv_kernel<<<(n_out + TILE_M - 1) / TILE_M, CONV_THREADS, CONV_SMEM>>>(x, w, nidx, n_out);
    finalize_kernel<<<1, 64>>>(gamma, beta, 1.0f / (float)n_out);
    pool_kernel<<<(n_pool * 16 + 255) / 256, 256>>>(pidx, out, n_pool);

    int extra = out_size - n_pool * COUT;
    if (extra > 0 && depth) {
        depth_kernel<<<(extra + 255) / 256, 256>>>(out + (size_t)n_pool * COUT, depth, extra);
    }
}